// round 12
// baseline (speedup 1.0000x reference)
#include <cuda_runtime.h>
#include <math_constants.h>

// Fixed problem shape: B=16, R=Hr*Wr=4096, Q=Hq*Wq=1024
#define R 4096
#define Q 1024
#define MAXB 16
#define RCHUNK 64
#define NCHUNK (R / RCHUNK)     // 64 chunks per batch
#define NBLK 32                 // 32 column-blocks of 32 columns each
#define LOG2E 1.4426950408889634f
#define M2SCALE 32.0f
#define M2INV   0.03125f
#define P2ROWS 8                // rows per warp in pass 2

// Static device scratch
__device__ float  g_colsum[MAXB * Q];                         // 64 KB atomic column sums
__device__ float  g_creflog[MAXB * Q];                        // 64 KB log column sums
__device__ float  g_cmin[MAXB * NBLK];                        // per-32col min Cref
__device__ float  g_bm[(size_t)MAXB * R * NBLK];              // 8 MB per-row block max (exact)
__device__ unsigned short g_aux[(size_t)MAXB * R * NBLK];     // 4 MB packed (d<<8)|witness
__device__ float  g_rs[MAXB * R];                             // row sums of exp(aq*x)

__device__ __forceinline__ float ex2f(float t) {
    float r;
    asm("ex2.approx.ftz.f32 %0, %1;" : "=f"(r) : "f"(t));
    return r;
}

// ---------------------------------------------------------------------------
// Zero the atomic column-sum buffer (runs before pass1 each launch).
// ---------------------------------------------------------------------------
__global__ void qatm_zero()
{
    g_colsum[blockIdx.x * 1024 + threadIdx.x] = 0.f;
}

// ---------------------------------------------------------------------------
// Pass 1 (unchanged from R11): stream x once per 64-row chunk; thread t owns
// columns 4t..4t+3. 8 rows in flight (MLP 8), x via __ldcg. Per 32-col block:
// TOP-2 maxes (m1 + witness index, m2) + 32-col partial row sums, one shared
// 3-level butterfly. Column sums leave via red.global.add (L2-resident).
// ---------------------------------------------------------------------------
__global__ __launch_bounds__(256) void qatm_pass1(
    const float* __restrict__ x,
    const float* __restrict__ cr,
    const float* __restrict__ cq)
{
    __shared__ float s_bm[RCHUNK * NBLK];                      // 8 KB [row][j] top-1
    __shared__ float s_bm2[RCHUNK * NBLK];                     // 8 KB [row][j] top-2
    __shared__ float s_rs32[RCHUNK * NBLK];                    // 8 KB [row][j] partial rs
    __shared__ __align__(8) unsigned char s_bi[RCHUNK * NBLK]; // 2 KB [row][j]

    const int b    = blockIdx.x >> 6;
    const int c    = blockIdx.x & (NCHUNK - 1);
    const int t    = threadIdx.x;
    const int lane = t & 31;
    const int g    = t >> 3;                 // column-block 0..31 owned by thread
    const int l8   = 4 * (lane & 7);         // base idx of this thread within block

    const float ar  = cr[0];
    const float aq  = cq[0];
    const bool same = (ar == aq);
    const float arl = ar * LOG2E;
    const float aql = aq * LOG2E;

    const float4* p = reinterpret_cast<const float4*>(
        x + ((size_t)b * R + (size_t)c * RCHUNK) * Q) + t;

    float4 acc = make_float4(0.f, 0.f, 0.f, 0.f);

    #pragma unroll 1
    for (int r = 0; r < RCHUNK; r += 8) {
        float4 v[8];
        #pragma unroll
        for (int k = 0; k < 8; ++k)
            v[k] = __ldcg(p + k * (Q / 4));
        p += 8 * (Q / 4);

        #pragma unroll
        for (int k = 0; k < 8; ++k) {
            float4 w = v[k];

            float e0 = ex2f(arl * w.x);
            float e1 = ex2f(arl * w.y);
            float e2 = ex2f(arl * w.z);
            float e3 = ex2f(arl * w.w);
            acc.x += e0; acc.y += e1; acc.z += e2; acc.w += e3;

            float rsl;
            if (same) {
                rsl = (e0 + e1) + (e2 + e3);
            } else {
                rsl = ex2f(aql * w.x) + ex2f(aql * w.y)
                    + ex2f(aql * w.z) + ex2f(aql * w.w);
            }

            // per-thread top-2 of the 4 components
            float hi1 = fmaxf(w.x, w.y), lo1 = fminf(w.x, w.y);
            float hi2 = fmaxf(w.z, w.w), lo2 = fminf(w.z, w.w);
            float m1 = fmaxf(hi1, hi2);
            float m2 = fmaxf(fminf(hi1, hi2), fmaxf(lo1, lo2));

            // shared 3-level butterfly (8 lanes = 32 columns): rs + exact top-2
            #pragma unroll
            for (int o = 4; o > 0; o >>= 1) {
                rsl += __shfl_xor_sync(0xFFFFFFFFu, rsl, o);
                float om1 = __shfl_xor_sync(0xFFFFFFFFu, m1, o);
                float om2 = __shfl_xor_sync(0xFFFFFFFFu, m2, o);
                m2 = fmaxf(fminf(m1, om1), fmaxf(m2, om2));
                m1 = fmaxf(m1, om1);
            }

            // witness index: some lane's component equals m1 exactly
            int idx = -1;
            if (w.x == m1) idx = l8;
            if (w.y == m1) idx = l8 + 1;
            if (w.z == m1) idx = l8 + 2;
            if (w.w == m1) idx = l8 + 3;
            if (idx >= 0) s_bi[(r + k) * NBLK + g] = (unsigned char)idx;

            if ((lane & 7) == 0) {
                s_bm[(r + k) * NBLK + g]   = m1;
                s_bm2[(r + k) * NBLK + g]  = m2;
                s_rs32[(r + k) * NBLK + g] = rsl;
            }
        }
    }
    __syncthreads();

    // column sums -> L2-resident atomic accumulator (64 KB total)
    float* cs = g_colsum + (size_t)b * Q + 4 * t;
    atomicAdd(cs + 0, acc.x);
    atomicAdd(cs + 1, acc.y);
    atomicAdd(cs + 2, acc.z);
    atomicAdd(cs + 3, acc.w);

    // finish row sums: thread t<64 sums 32 partials of row t (rotated)
    if (t < RCHUNK) {
        float s = 0.f;
        #pragma unroll
        for (int i = 0; i < NBLK; ++i)
            s += s_rs32[t * NBLK + ((i + t) & (NBLK - 1))];
        g_rs[b * R + c * RCHUNK + t] = s;
    }

    // headers out: exact m1 (float) + packed (quantized m2 delta, witness)
    const size_t rowbase = (size_t)b * R + (size_t)c * RCHUNK;
    float4* gbm = reinterpret_cast<float4*>(g_bm + rowbase * NBLK);
    const float4* sb = reinterpret_cast<const float4*>(s_bm);
    gbm[t]       = sb[t];
    gbm[t + 256] = sb[t + 256];

    // pack 8 entries per thread: aux = (d << 8) | bi, d = floor((m1-m2)*32) sat
    {
        unsigned int pk[4];
        #pragma unroll
        for (int i = 0; i < 4; ++i) {
            int e0 = 8 * t + 2 * i;
            float d0f = (s_bm[e0] - s_bm2[e0]) * M2SCALE;
            float d1f = (s_bm[e0 + 1] - s_bm2[e0 + 1]) * M2SCALE;
            unsigned int d0 = min(255u, (unsigned int)d0f);   // floor: bound stays valid
            unsigned int d1 = min(255u, (unsigned int)d1f);
            unsigned int a0 = (d0 << 8) | s_bi[e0];
            unsigned int a1 = (d1 << 8) | s_bi[e0 + 1];
            pk[i] = a0 | (a1 << 16);
        }
        reinterpret_cast<uint4*>(g_aux + rowbase * NBLK)[t] =
            make_uint4(pk[0], pk[1], pk[2], pk[3]);
    }
}

// ---------------------------------------------------------------------------
// Kernel 2: Cref = log(colsum) from the L2-resident accumulator; per-32-col Cmin.
// ---------------------------------------------------------------------------
__global__ __launch_bounds__(256) void qatm_cred()
{
    const int b    = blockIdx.x >> 2;
    const int col  = ((blockIdx.x & 3) << 8) + threadIdx.x;
    const int lane = threadIdx.x & 31;

    float lg = __logf(g_colsum[b * Q + col]);
    g_creflog[b * Q + col] = lg;

    float mn = lg;
    #pragma unroll
    for (int o = 16; o > 0; o >>= 1)
        mn = fminf(mn, __shfl_xor_sync(0xFFFFFFFFu, mn, o));
    if (lane == 0)
        g_cmin[b * NBLK + (col >> 5)] = mn;
}

// ---------------------------------------------------------------------------
// Pass 2: warp per EIGHT rows. All header loads for 8 rows issued
// independently up front (round 1), 8 independent witness gathers (round 2),
// joint survivor drain across the 8 masks (round 3+, MLP 8).
//   lb = max_j (cc*bm_j - Cref[witness_j])       (witness value exact)
//   block j scanned ONLY if cc*(bm_j - d_j/32) - Cmin_j > lb.
// ---------------------------------------------------------------------------
__global__ __launch_bounds__(256) void qatm_p2(
    const float* __restrict__ x,
    const float* __restrict__ cr,
    const float* __restrict__ cq,
    float* __restrict__ out)
{
    const int wid  = threadIdx.x >> 5;
    const int lane = threadIdx.x & 31;
    const int row0 = (blockIdx.x * 8 + wid) * P2ROWS;
    const int b    = row0 >> 12;           // 8 consecutive rows share a batch

    const float cc = cr[0] + cq[0];
    const float* cl = g_creflog + (size_t)b * Q;

    const float cmin = __ldg(&g_cmin[b * NBLK + lane]);

    // round 1: all header loads independent
    float bm[P2ROWS];
    unsigned int ax[P2ROWS];
    #pragma unroll
    for (int r = 0; r < P2ROWS; ++r)
        bm[r] = g_bm[(size_t)(row0 + r) * NBLK + lane];
    #pragma unroll
    for (int r = 0; r < P2ROWS; ++r)
        ax[r] = g_aux[(size_t)(row0 + r) * NBLK + lane];
    float rr = (lane < P2ROWS) ? __ldg(&g_rs[row0 + lane]) : 1.f;

    // round 2: witness Cref gathers (all independent)
    float cw[P2ROWS];
    #pragma unroll
    for (int r = 0; r < P2ROWS; ++r)
        cw[r] = __ldg(cl + lane * 32 + (ax[r] & 255u));

    // exact witness values -> per-row lb; quantized second-max upper bounds
    float m[P2ROWS];
    unsigned k[P2ROWS];
    #pragma unroll
    for (int r = 0; r < P2ROWS; ++r)
        m[r] = fmaf(cc, bm[r], -cw[r]);

    #pragma unroll
    for (int o = 16; o > 0; o >>= 1) {
        #pragma unroll
        for (int r = 0; r < P2ROWS; ++r)
            m[r] = fmaxf(m[r], __shfl_xor_sync(0xFFFFFFFFu, m[r], o));
    }

    #pragma unroll
    for (int r = 0; r < P2ROWS; ++r) {
        float s = bm[r] - (float)(ax[r] >> 8) * M2INV;   // >= true second max
        k[r] = __ballot_sync(0xFFFFFFFFu, fmaf(cc, s, -cmin) > m[r]);
    }

    // round 3+: joint survivor drain, up to 8 independent x loads per round
    unsigned any = k[0] | k[1] | k[2] | k[3] | k[4] | k[5] | k[6] | k[7];
    while (any) {
        int j[P2ROWS];
        #pragma unroll
        for (int r = 0; r < P2ROWS; ++r) {
            j[r] = -1;
            if (k[r]) { j[r] = __ffs(k[r]) - 1; k[r] &= k[r] - 1; }
        }
        float a[P2ROWS], cf[P2ROWS];
        #pragma unroll
        for (int r = 0; r < P2ROWS; ++r)
            a[r] = (j[r] >= 0) ? __ldcs(x + (size_t)(row0 + r) * Q + j[r] * 32 + lane) : 0.f;
        #pragma unroll
        for (int r = 0; r < P2ROWS; ++r)
            cf[r] = (j[r] >= 0) ? __ldg(cl + j[r] * 32 + lane) : 0.f;
        #pragma unroll
        for (int r = 0; r < P2ROWS; ++r)
            if (j[r] >= 0) m[r] = fmaxf(m[r], fmaf(cc, a[r], -cf[r]));
        any = k[0] | k[1] | k[2] | k[3] | k[4] | k[5] | k[6] | k[7];
    }

    #pragma unroll
    for (int o = 16; o > 0; o >>= 1) {
        #pragma unroll
        for (int r = 0; r < P2ROWS; ++r)
            m[r] = fmaxf(m[r], __shfl_xor_sync(0xFFFFFFFFu, m[r], o));
    }

    if (lane < P2ROWS) {
        float mm = m[0];
        #pragma unroll
        for (int r = 1; r < P2ROWS; ++r)
            if (lane == r) mm = m[r];
        out[row0 + lane] = __expf(0.5f * (mm - __logf(rr)));
    }
}

// ---------------------------------------------------------------------------
extern "C" void kernel_launch(void* const* d_in, const int* in_sizes, int n_in,
                              void* d_out, int out_size)
{
    const float* x  = (const float*)d_in[0];
    const float* cr = (const float*)d_in[1];
    const float* cq = (const float*)d_in[2];
    float* out = (float*)d_out;

    const int B = in_sizes[0] / (R * Q);   // 16

    qatm_zero<<<MAXB, 1024>>>();
    qatm_pass1<<<B * NCHUNK, 256>>>(x, cr, cq);
    qatm_cred<<<B * 4, 256>>>();
    qatm_p2<<<B * R / (8 * P2ROWS), 256>>>(x, cr, cq, out);
}

// round 13
// speedup vs baseline: 1.0226x; 1.0226x over previous
#include <cuda_runtime.h>
#include <math_constants.h>

// Fixed problem shape: B=16, R=Hr*Wr=4096, Q=Hq*Wq=1024
#define R 4096
#define Q 1024
#define MAXB 16
#define RCHUNK 64
#define NCHUNK (R / RCHUNK)     // 64 chunks per batch
#define NBLK 32                 // 32 column-blocks of 32 columns each
#define LOG2E 1.4426950408889634f
#define M2SCALE 32.0f
#define M2INV   0.03125f
#define P2ROWS 8                // rows per warp in pass 2

// Static device scratch
__device__ float  g_colsum[MAXB * Q];                         // 64 KB atomic column sums
__device__ float  g_creflog[MAXB * Q];                        // 64 KB log column sums
__device__ float  g_cmin[MAXB * NBLK];                        // per-32col min Cref
__device__ float  g_bm[(size_t)MAXB * R * NBLK];              // 8 MB per-row block max (exact)
__device__ unsigned short g_aux[(size_t)MAXB * R * NBLK];     // 4 MB packed (d<<8)|witness
__device__ float  g_rs[MAXB * R];                             // row sums of exp(aq*x)

__device__ __forceinline__ float ex2f(float t) {
    float r;
    asm("ex2.approx.ftz.f32 %0, %1;" : "=f"(r) : "f"(t));
    return r;
}

// ---------------------------------------------------------------------------
// Zero the atomic column-sum buffer (runs before pass1 each launch).
// ---------------------------------------------------------------------------
__global__ void qatm_zero()
{
    g_colsum[blockIdx.x * 1024 + threadIdx.x] = 0.f;
}

// ---------------------------------------------------------------------------
// Pass 1 (unchanged from R11): stream x once per 64-row chunk; thread t owns
// columns 4t..4t+3. 8 rows in flight (MLP 8), x via __ldcg. Per 32-col block:
// TOP-2 maxes (m1 + witness index, m2) + 32-col partial row sums, one shared
// 3-level butterfly. Column sums leave via red.global.add (L2-resident).
// ---------------------------------------------------------------------------
__global__ __launch_bounds__(256) void qatm_pass1(
    const float* __restrict__ x,
    const float* __restrict__ cr,
    const float* __restrict__ cq)
{
    __shared__ float s_bm[RCHUNK * NBLK];                      // 8 KB [row][j] top-1
    __shared__ float s_bm2[RCHUNK * NBLK];                     // 8 KB [row][j] top-2
    __shared__ float s_rs32[RCHUNK * NBLK];                    // 8 KB [row][j] partial rs
    __shared__ __align__(8) unsigned char s_bi[RCHUNK * NBLK]; // 2 KB [row][j]

    const int b    = blockIdx.x >> 6;
    const int c    = blockIdx.x & (NCHUNK - 1);
    const int t    = threadIdx.x;
    const int lane = t & 31;
    const int g    = t >> 3;                 // column-block 0..31 owned by thread
    const int l8   = 4 * (lane & 7);         // base idx of this thread within block

    const float ar  = cr[0];
    const float aq  = cq[0];
    const bool same = (ar == aq);
    const float arl = ar * LOG2E;
    const float aql = aq * LOG2E;

    const float4* p = reinterpret_cast<const float4*>(
        x + ((size_t)b * R + (size_t)c * RCHUNK) * Q) + t;

    float4 acc = make_float4(0.f, 0.f, 0.f, 0.f);

    #pragma unroll 1
    for (int r = 0; r < RCHUNK; r += 8) {
        float4 v[8];
        #pragma unroll
        for (int k = 0; k < 8; ++k)
            v[k] = __ldcg(p + k * (Q / 4));
        p += 8 * (Q / 4);

        #pragma unroll
        for (int k = 0; k < 8; ++k) {
            float4 w = v[k];

            float e0 = ex2f(arl * w.x);
            float e1 = ex2f(arl * w.y);
            float e2 = ex2f(arl * w.z);
            float e3 = ex2f(arl * w.w);
            acc.x += e0; acc.y += e1; acc.z += e2; acc.w += e3;

            float rsl;
            if (same) {
                rsl = (e0 + e1) + (e2 + e3);
            } else {
                rsl = ex2f(aql * w.x) + ex2f(aql * w.y)
                    + ex2f(aql * w.z) + ex2f(aql * w.w);
            }

            // per-thread top-2 of the 4 components
            float hi1 = fmaxf(w.x, w.y), lo1 = fminf(w.x, w.y);
            float hi2 = fmaxf(w.z, w.w), lo2 = fminf(w.z, w.w);
            float m1 = fmaxf(hi1, hi2);
            float m2 = fmaxf(fminf(hi1, hi2), fmaxf(lo1, lo2));

            // shared 3-level butterfly (8 lanes = 32 columns): rs + exact top-2
            #pragma unroll
            for (int o = 4; o > 0; o >>= 1) {
                rsl += __shfl_xor_sync(0xFFFFFFFFu, rsl, o);
                float om1 = __shfl_xor_sync(0xFFFFFFFFu, m1, o);
                float om2 = __shfl_xor_sync(0xFFFFFFFFu, m2, o);
                m2 = fmaxf(fminf(m1, om1), fmaxf(m2, om2));
                m1 = fmaxf(m1, om1);
            }

            // witness index: some lane's component equals m1 exactly
            int idx = -1;
            if (w.x == m1) idx = l8;
            if (w.y == m1) idx = l8 + 1;
            if (w.z == m1) idx = l8 + 2;
            if (w.w == m1) idx = l8 + 3;
            if (idx >= 0) s_bi[(r + k) * NBLK + g] = (unsigned char)idx;

            if ((lane & 7) == 0) {
                s_bm[(r + k) * NBLK + g]   = m1;
                s_bm2[(r + k) * NBLK + g]  = m2;
                s_rs32[(r + k) * NBLK + g] = rsl;
            }
        }
    }
    __syncthreads();

    // column sums -> L2-resident atomic accumulator (64 KB total)
    float* cs = g_colsum + (size_t)b * Q + 4 * t;
    atomicAdd(cs + 0, acc.x);
    atomicAdd(cs + 1, acc.y);
    atomicAdd(cs + 2, acc.z);
    atomicAdd(cs + 3, acc.w);

    // finish row sums: thread t<64 sums 32 partials of row t (rotated)
    if (t < RCHUNK) {
        float s = 0.f;
        #pragma unroll
        for (int i = 0; i < NBLK; ++i)
            s += s_rs32[t * NBLK + ((i + t) & (NBLK - 1))];
        g_rs[b * R + c * RCHUNK + t] = s;
    }

    // headers out: exact m1 (float) + packed (quantized m2 delta, witness)
    const size_t rowbase = (size_t)b * R + (size_t)c * RCHUNK;
    float4* gbm = reinterpret_cast<float4*>(g_bm + rowbase * NBLK);
    const float4* sb = reinterpret_cast<const float4*>(s_bm);
    gbm[t]       = sb[t];
    gbm[t + 256] = sb[t + 256];

    // pack 8 entries per thread: aux = (d << 8) | bi, d = floor((m1-m2)*32) sat
    {
        unsigned int pk[4];
        #pragma unroll
        for (int i = 0; i < 4; ++i) {
            int e0 = 8 * t + 2 * i;
            float d0f = (s_bm[e0] - s_bm2[e0]) * M2SCALE;
            float d1f = (s_bm[e0 + 1] - s_bm2[e0 + 1]) * M2SCALE;
            unsigned int d0 = min(255u, (unsigned int)d0f);   // floor: bound stays valid
            unsigned int d1 = min(255u, (unsigned int)d1f);
            unsigned int a0 = (d0 << 8) | s_bi[e0];
            unsigned int a1 = (d1 << 8) | s_bi[e0 + 1];
            pk[i] = a0 | (a1 << 16);
        }
        reinterpret_cast<uint4*>(g_aux + rowbase * NBLK)[t] =
            make_uint4(pk[0], pk[1], pk[2], pk[3]);
    }
}

// ---------------------------------------------------------------------------
// Kernel 2: Cref = log(colsum) from the L2-resident accumulator; per-32-col Cmin.
// ---------------------------------------------------------------------------
__global__ __launch_bounds__(256) void qatm_cred()
{
    const int b    = blockIdx.x >> 2;
    const int col  = ((blockIdx.x & 3) << 8) + threadIdx.x;
    const int lane = threadIdx.x & 31;

    float lg = __logf(g_colsum[b * Q + col]);
    g_creflog[b * Q + col] = lg;

    float mn = lg;
    #pragma unroll
    for (int o = 16; o > 0; o >>= 1)
        mn = fminf(mn, __shfl_xor_sync(0xFFFFFFFFu, mn, o));
    if (lane == 0)
        g_cmin[b * NBLK + (col >> 5)] = mn;
}

// ---------------------------------------------------------------------------
// Pass 2: warp per EIGHT rows; block covers 64 rows of one batch.
// The batch's Cref table (4 KB) is staged in shared memory once per block —
// the witness gather becomes an LDS scatter (bank-conflict ~2-4) instead of
// a 32-line L1tex scatter, and survivor Cref reads are conflict-free LDS.
//   lb = max_j (cc*bm_j - Cref[witness_j])       (witness value exact)
//   block j scanned ONLY if cc*(bm_j - d_j/32) - Cmin_j > lb.
// ---------------------------------------------------------------------------
__global__ __launch_bounds__(256) void qatm_p2(
    const float* __restrict__ x,
    const float* __restrict__ cr,
    const float* __restrict__ cq,
    float* __restrict__ out)
{
    __shared__ __align__(16) float s_clog[Q];   // this batch's Cref table

    const int wid  = threadIdx.x >> 5;
    const int lane = threadIdx.x & 31;
    const int row0 = (blockIdx.x * 8 + wid) * P2ROWS;
    const int b    = row0 >> 12;           // all 64 block rows share a batch

    // stage Cref (coalesced): 256 threads x 1 float4
    reinterpret_cast<float4*>(s_clog)[threadIdx.x] =
        reinterpret_cast<const float4*>(g_creflog + (size_t)b * Q)[threadIdx.x];
    __syncthreads();

    const float cc = cr[0] + cq[0];
    const float cmin = __ldg(&g_cmin[b * NBLK + lane]);

    // round 1: all header loads independent
    float bm[P2ROWS];
    unsigned int ax[P2ROWS];
    #pragma unroll
    for (int r = 0; r < P2ROWS; ++r)
        bm[r] = g_bm[(size_t)(row0 + r) * NBLK + lane];
    #pragma unroll
    for (int r = 0; r < P2ROWS; ++r)
        ax[r] = g_aux[(size_t)(row0 + r) * NBLK + lane];
    float rr = (lane < P2ROWS) ? __ldg(&g_rs[row0 + lane]) : 1.f;

    // witness Cref via smem (bank = bi mod 32, mild conflicts)
    float cw[P2ROWS];
    #pragma unroll
    for (int r = 0; r < P2ROWS; ++r)
        cw[r] = s_clog[lane * 32 + (ax[r] & 255u)];

    // exact witness values -> per-row lb; quantized second-max upper bounds
    float m[P2ROWS];
    unsigned k[P2ROWS];
    #pragma unroll
    for (int r = 0; r < P2ROWS; ++r)
        m[r] = fmaf(cc, bm[r], -cw[r]);

    #pragma unroll
    for (int o = 16; o > 0; o >>= 1) {
        #pragma unroll
        for (int r = 0; r < P2ROWS; ++r)
            m[r] = fmaxf(m[r], __shfl_xor_sync(0xFFFFFFFFu, m[r], o));
    }

    #pragma unroll
    for (int r = 0; r < P2ROWS; ++r) {
        float s = bm[r] - (float)(ax[r] >> 8) * M2INV;   // >= true second max
        k[r] = __ballot_sync(0xFFFFFFFFu, fmaf(cc, s, -cmin) > m[r]);
    }

    // survivor drain: up to 8 independent x loads per round; Cref from smem
    unsigned any = k[0] | k[1] | k[2] | k[3] | k[4] | k[5] | k[6] | k[7];
    while (any) {
        int j[P2ROWS];
        #pragma unroll
        for (int r = 0; r < P2ROWS; ++r) {
            j[r] = -1;
            if (k[r]) { j[r] = __ffs(k[r]) - 1; k[r] &= k[r] - 1; }
        }
        float a[P2ROWS];
        #pragma unroll
        for (int r = 0; r < P2ROWS; ++r)
            a[r] = (j[r] >= 0) ? __ldcs(x + (size_t)(row0 + r) * Q + j[r] * 32 + lane) : 0.f;
        #pragma unroll
        for (int r = 0; r < P2ROWS; ++r)
            if (j[r] >= 0) {
                float cf = s_clog[j[r] * 32 + lane];   // conflict-free LDS
                m[r] = fmaxf(m[r], fmaf(cc, a[r], -cf));
            }
        any = k[0] | k[1] | k[2] | k[3] | k[4] | k[5] | k[6] | k[7];
    }

    #pragma unroll
    for (int o = 16; o > 0; o >>= 1) {
        #pragma unroll
        for (int r = 0; r < P2ROWS; ++r)
            m[r] = fmaxf(m[r], __shfl_xor_sync(0xFFFFFFFFu, m[r], o));
    }

    if (lane < P2ROWS) {
        float mm = m[0];
        #pragma unroll
        for (int r = 1; r < P2ROWS; ++r)
            if (lane == r) mm = m[r];
        out[row0 + lane] = __expf(0.5f * (mm - __logf(rr)));
    }
}

// ---------------------------------------------------------------------------
extern "C" void kernel_launch(void* const* d_in, const int* in_sizes, int n_in,
                              void* d_out, int out_size)
{
    const float* x  = (const float*)d_in[0];
    const float* cr = (const float*)d_in[1];
    const float* cq = (const float*)d_in[2];
    float* out = (float*)d_out;

    const int B = in_sizes[0] / (R * Q);   // 16

    qatm_zero<<<MAXB, 1024>>>();
    qatm_pass1<<<B * NCHUNK, 256>>>(x, cr, cq);
    qatm_cred<<<B * 4, 256>>>();
    qatm_p2<<<B * R / (8 * P2ROWS), 256>>>(x, cr, cq, out);
}

// round 14
// speedup vs baseline: 1.0293x; 1.0066x over previous
#include <cuda_runtime.h>
#include <math_constants.h>

// Fixed problem shape: B=16, R=Hr*Wr=4096, Q=Hq*Wq=1024
#define R 4096
#define Q 1024
#define MAXB 16
#define RCHUNK 64
#define NCHUNK (R / RCHUNK)     // 64 chunks per batch
#define NBLK 32                 // 32 column-blocks of 32 columns each
#define LOG2E 1.4426950408889634f
#define M2SCALE 32.0f
#define M2INV   0.03125f
#define P2ROWS 8                // rows per warp in pass 2

// Static device scratch. g_colsum is zero at module load and is re-zeroed by
// qatm_cred after each read, so every launch sees zeros (graph-replay safe).
__device__ float  g_colsum[MAXB * Q];                         // 64 KB atomic column sums
__device__ float  g_creflog[MAXB * Q];                        // 64 KB log column sums
__device__ float  g_cmin[MAXB * NBLK];                        // per-32col min Cref
__device__ float  g_bm[(size_t)MAXB * R * NBLK];              // 8 MB per-row block max (exact)
__device__ unsigned short g_aux[(size_t)MAXB * R * NBLK];     // 4 MB packed (d<<8)|witness
__device__ float  g_rs[MAXB * R];                             // row sums of exp(aq*x)

__device__ __forceinline__ float ex2f(float t) {
    float r;
    asm("ex2.approx.ftz.f32 %0, %1;" : "=f"(r) : "f"(t));
    return r;
}

// ---------------------------------------------------------------------------
// Pass 1 (unchanged): stream x once per 64-row chunk; thread t owns columns
// 4t..4t+3. 8 rows in flight (MLP 8), x via __ldcg. Per 32-col block: TOP-2
// maxes (m1 + witness index, m2) + 32-col partial row sums, one shared
// 3-level butterfly. Column sums leave via red.global.add (L2-resident).
// ---------------------------------------------------------------------------
__global__ __launch_bounds__(256) void qatm_pass1(
    const float* __restrict__ x,
    const float* __restrict__ cr,
    const float* __restrict__ cq)
{
    __shared__ float s_bm[RCHUNK * NBLK];                      // 8 KB [row][j] top-1
    __shared__ float s_bm2[RCHUNK * NBLK];                     // 8 KB [row][j] top-2
    __shared__ float s_rs32[RCHUNK * NBLK];                    // 8 KB [row][j] partial rs
    __shared__ __align__(8) unsigned char s_bi[RCHUNK * NBLK]; // 2 KB [row][j]

    const int b    = blockIdx.x >> 6;
    const int c    = blockIdx.x & (NCHUNK - 1);
    const int t    = threadIdx.x;
    const int lane = t & 31;
    const int g    = t >> 3;                 // column-block 0..31 owned by thread
    const int l8   = 4 * (lane & 7);         // base idx of this thread within block

    const float ar  = cr[0];
    const float aq  = cq[0];
    const bool same = (ar == aq);
    const float arl = ar * LOG2E;
    const float aql = aq * LOG2E;

    const float4* p = reinterpret_cast<const float4*>(
        x + ((size_t)b * R + (size_t)c * RCHUNK) * Q) + t;

    float4 acc = make_float4(0.f, 0.f, 0.f, 0.f);

    #pragma unroll 1
    for (int r = 0; r < RCHUNK; r += 8) {
        float4 v[8];
        #pragma unroll
        for (int k = 0; k < 8; ++k)
            v[k] = __ldcg(p + k * (Q / 4));
        p += 8 * (Q / 4);

        #pragma unroll
        for (int k = 0; k < 8; ++k) {
            float4 w = v[k];

            float e0 = ex2f(arl * w.x);
            float e1 = ex2f(arl * w.y);
            float e2 = ex2f(arl * w.z);
            float e3 = ex2f(arl * w.w);
            acc.x += e0; acc.y += e1; acc.z += e2; acc.w += e3;

            float rsl;
            if (same) {
                rsl = (e0 + e1) + (e2 + e3);
            } else {
                rsl = ex2f(aql * w.x) + ex2f(aql * w.y)
                    + ex2f(aql * w.z) + ex2f(aql * w.w);
            }

            // per-thread top-2 of the 4 components
            float hi1 = fmaxf(w.x, w.y), lo1 = fminf(w.x, w.y);
            float hi2 = fmaxf(w.z, w.w), lo2 = fminf(w.z, w.w);
            float m1 = fmaxf(hi1, hi2);
            float m2 = fmaxf(fminf(hi1, hi2), fmaxf(lo1, lo2));

            // shared 3-level butterfly (8 lanes = 32 columns): rs + exact top-2
            #pragma unroll
            for (int o = 4; o > 0; o >>= 1) {
                rsl += __shfl_xor_sync(0xFFFFFFFFu, rsl, o);
                float om1 = __shfl_xor_sync(0xFFFFFFFFu, m1, o);
                float om2 = __shfl_xor_sync(0xFFFFFFFFu, m2, o);
                m2 = fmaxf(fminf(m1, om1), fmaxf(m2, om2));
                m1 = fmaxf(m1, om1);
            }

            // witness index: some lane's component equals m1 exactly
            int idx = -1;
            if (w.x == m1) idx = l8;
            if (w.y == m1) idx = l8 + 1;
            if (w.z == m1) idx = l8 + 2;
            if (w.w == m1) idx = l8 + 3;
            if (idx >= 0) s_bi[(r + k) * NBLK + g] = (unsigned char)idx;

            if ((lane & 7) == 0) {
                s_bm[(r + k) * NBLK + g]   = m1;
                s_bm2[(r + k) * NBLK + g]  = m2;
                s_rs32[(r + k) * NBLK + g] = rsl;
            }
        }
    }
    __syncthreads();

    // column sums -> L2-resident atomic accumulator (64 KB total)
    float* cs = g_colsum + (size_t)b * Q + 4 * t;
    atomicAdd(cs + 0, acc.x);
    atomicAdd(cs + 1, acc.y);
    atomicAdd(cs + 2, acc.z);
    atomicAdd(cs + 3, acc.w);

    // finish row sums: thread t<64 sums 32 partials of row t (rotated)
    if (t < RCHUNK) {
        float s = 0.f;
        #pragma unroll
        for (int i = 0; i < NBLK; ++i)
            s += s_rs32[t * NBLK + ((i + t) & (NBLK - 1))];
        g_rs[b * R + c * RCHUNK + t] = s;
    }

    // headers out: exact m1 (float) + packed (quantized m2 delta, witness)
    const size_t rowbase = (size_t)b * R + (size_t)c * RCHUNK;
    float4* gbm = reinterpret_cast<float4*>(g_bm + rowbase * NBLK);
    const float4* sb = reinterpret_cast<const float4*>(s_bm);
    gbm[t]       = sb[t];
    gbm[t + 256] = sb[t + 256];

    // pack 8 entries per thread: aux = (d << 8) | bi, d = floor((m1-m2)*32) sat
    {
        unsigned int pk[4];
        #pragma unroll
        for (int i = 0; i < 4; ++i) {
            int e0 = 8 * t + 2 * i;
            float d0f = (s_bm[e0] - s_bm2[e0]) * M2SCALE;
            float d1f = (s_bm[e0 + 1] - s_bm2[e0 + 1]) * M2SCALE;
            unsigned int d0 = min(255u, (unsigned int)d0f);   // floor: bound stays valid
            unsigned int d1 = min(255u, (unsigned int)d1f);
            unsigned int a0 = (d0 << 8) | s_bi[e0];
            unsigned int a1 = (d1 << 8) | s_bi[e0 + 1];
            pk[i] = a0 | (a1 << 16);
        }
        reinterpret_cast<uint4*>(g_aux + rowbase * NBLK)[t] =
            make_uint4(pk[0], pk[1], pk[2], pk[3]);
    }
}

// ---------------------------------------------------------------------------
// Kernel 2: Cref = log(colsum); per-32-col Cmin. Re-zeroes g_colsum after
// reading so the next launch (graph replay) starts from zeros again.
// ---------------------------------------------------------------------------
__global__ __launch_bounds__(256) void qatm_cred()
{
    const int b    = blockIdx.x >> 2;
    const int col  = ((blockIdx.x & 3) << 8) + threadIdx.x;
    const int lane = threadIdx.x & 31;

    float s = g_colsum[b * Q + col];
    g_colsum[b * Q + col] = 0.f;          // reset for next launch

    float lg = __logf(s);
    g_creflog[b * Q + col] = lg;

    float mn = lg;
    #pragma unroll
    for (int o = 16; o > 0; o >>= 1)
        mn = fminf(mn, __shfl_xor_sync(0xFFFFFFFFu, mn, o));
    if (lane == 0)
        g_cmin[b * NBLK + (col >> 5)] = mn;
}

// ---------------------------------------------------------------------------
// Pass 2: warp per EIGHT rows; block covers 64 rows of one batch.
// Batch Cref table staged in smem. Witness gather = LDS scatter; survivor
// Cref reads conflict-free LDS. Final per-row butterfly only for rows that
// actually had survivors (others already hold the warp-uniform lb).
// ---------------------------------------------------------------------------
__global__ __launch_bounds__(256) void qatm_p2(
    const float* __restrict__ x,
    const float* __restrict__ cr,
    const float* __restrict__ cq,
    float* __restrict__ out)
{
    __shared__ __align__(16) float s_clog[Q];   // this batch's Cref table

    const int wid  = threadIdx.x >> 5;
    const int lane = threadIdx.x & 31;
    const int row0 = (blockIdx.x * 8 + wid) * P2ROWS;
    const int b    = row0 >> 12;           // all 64 block rows share a batch

    // stage Cref (coalesced): 256 threads x 1 float4
    reinterpret_cast<float4*>(s_clog)[threadIdx.x] =
        reinterpret_cast<const float4*>(g_creflog + (size_t)b * Q)[threadIdx.x];
    __syncthreads();

    const float cc = cr[0] + cq[0];
    const float cmin = __ldg(&g_cmin[b * NBLK + lane]);

    // round 1: all header loads independent
    float bm[P2ROWS];
    unsigned int ax[P2ROWS];
    #pragma unroll
    for (int r = 0; r < P2ROWS; ++r)
        bm[r] = g_bm[(size_t)(row0 + r) * NBLK + lane];
    #pragma unroll
    for (int r = 0; r < P2ROWS; ++r)
        ax[r] = g_aux[(size_t)(row0 + r) * NBLK + lane];
    float rr = (lane < P2ROWS) ? __ldg(&g_rs[row0 + lane]) : 1.f;

    // witness Cref via smem (bank = bi mod 32, mild conflicts)
    float cw[P2ROWS];
    #pragma unroll
    for (int r = 0; r < P2ROWS; ++r)
        cw[r] = s_clog[lane * 32 + (ax[r] & 255u)];

    // exact witness values -> per-row lb; quantized second-max upper bounds
    float m[P2ROWS];
    unsigned k[P2ROWS], had[P2ROWS];
    #pragma unroll
    for (int r = 0; r < P2ROWS; ++r)
        m[r] = fmaf(cc, bm[r], -cw[r]);

    #pragma unroll
    for (int o = 16; o > 0; o >>= 1) {
        #pragma unroll
        for (int r = 0; r < P2ROWS; ++r)
            m[r] = fmaxf(m[r], __shfl_xor_sync(0xFFFFFFFFu, m[r], o));
    }

    #pragma unroll
    for (int r = 0; r < P2ROWS; ++r) {
        float s = bm[r] - (float)(ax[r] >> 8) * M2INV;   // >= true second max
        k[r] = __ballot_sync(0xFFFFFFFFu, fmaf(cc, s, -cmin) > m[r]);
        had[r] = k[r];
    }

    // survivor drain: up to 8 independent x loads per round; Cref from smem
    unsigned any = k[0] | k[1] | k[2] | k[3] | k[4] | k[5] | k[6] | k[7];
    while (any) {
        int j[P2ROWS];
        #pragma unroll
        for (int r = 0; r < P2ROWS; ++r) {
            j[r] = -1;
            if (k[r]) { j[r] = __ffs(k[r]) - 1; k[r] &= k[r] - 1; }
        }
        float a[P2ROWS];
        #pragma unroll
        for (int r = 0; r < P2ROWS; ++r)
            a[r] = (j[r] >= 0) ? __ldcs(x + (size_t)(row0 + r) * Q + j[r] * 32 + lane) : 0.f;
        #pragma unroll
        for (int r = 0; r < P2ROWS; ++r)
            if (j[r] >= 0) {
                float cf = s_clog[j[r] * 32 + lane];   // conflict-free LDS
                m[r] = fmaxf(m[r], fmaf(cc, a[r], -cf));
            }
        any = k[0] | k[1] | k[2] | k[3] | k[4] | k[5] | k[6] | k[7];
    }

    // final reduce only where survivors touched m[r] (else m[r] is uniform lb)
    #pragma unroll
    for (int r = 0; r < P2ROWS; ++r) {
        if (had[r]) {
            #pragma unroll
            for (int o = 16; o > 0; o >>= 1)
                m[r] = fmaxf(m[r], __shfl_xor_sync(0xFFFFFFFFu, m[r], o));
        }
    }

    if (lane < P2ROWS) {
        float mm = m[0];
        #pragma unroll
        for (int r = 1; r < P2ROWS; ++r)
            if (lane == r) mm = m[r];
        out[row0 + lane] = __expf(0.5f * (mm - __logf(rr)));
    }
}

// ---------------------------------------------------------------------------
extern "C" void kernel_launch(void* const* d_in, const int* in_sizes, int n_in,
                              void* d_out, int out_size)
{
    const float* x  = (const float*)d_in[0];
    const float* cr = (const float*)d_in[1];
    const float* cq = (const float*)d_in[2];
    float* out = (float*)d_out;

    const int B = in_sizes[0] / (R * Q);   // 16

    qatm_pass1<<<B * NCHUNK, 256>>>(x, cr, cq);
    qatm_cred<<<B * 4, 256>>>();
    qatm_p2<<<B * R / (8 * P2ROWS), 256>>>(x, cr, cq, out);
}

// round 16
// speedup vs baseline: 1.0303x; 1.0009x over previous
#include <cuda_runtime.h>
#include <math_constants.h>

// Fixed problem shape: B=16, R=Hr*Wr=4096, Q=Hq*Wq=1024
#define R 4096
#define Q 1024
#define MAXB 16
#define RCHUNK 64
#define NCHUNK (R / RCHUNK)     // 64 chunks per batch
#define NBLK 32                 // 32 column-blocks of 32 columns each
#define LOG2E 1.4426950408889634f
#define M2SCALE 32.0f
#define M2INV   0.03125f
#define P2ROWS 8                // rows per warp in pass 2

// Static device scratch. g_colsum is zero at module load and is re-zeroed by
// qatm_cred after each read, so every launch sees zeros (graph-replay safe).
__device__ float  g_colsum[MAXB * Q];                         // 64 KB atomic column sums
__device__ float  g_creflog[MAXB * Q];                        // 64 KB log column sums
__device__ float  g_cmin[MAXB * NBLK];                        // per-32col min Cref
__device__ float  g_bm[(size_t)MAXB * R * NBLK];              // 8 MB per-row block max (exact)
__device__ unsigned short g_aux[(size_t)MAXB * R * NBLK];     // 4 MB packed (d<<8)|witness
__device__ float  g_rs[MAXB * R];                             // row sums of exp(aq*x)

__device__ __forceinline__ float ex2f(float t) {
    float r;
    asm("ex2.approx.ftz.f32 %0, %1;" : "=f"(r) : "f"(t));
    return r;
}

// ---------------------------------------------------------------------------
// Pass 1: stream x once per 64-row chunk; thread t owns columns 4t..4t+3.
// 8 rows in flight (MLP 8), x via __ldcg. Per 32-col block: TOP-2 maxes
// (m1 + witness index, m2) + 32-col partial row sums, one shared 3-level
// butterfly. Column sums leave via red.global.add (L2-resident).
// The witness is REQUIRED for correctness of pass-2 pruning: lb accounts for
// every block's top element exactly; the m2 bound covers only non-top ones.
// ---------------------------------------------------------------------------
__global__ __launch_bounds__(256) void qatm_pass1(
    const float* __restrict__ x,
    const float* __restrict__ cr,
    const float* __restrict__ cq)
{
    __shared__ float s_bm[RCHUNK * NBLK];                      // 8 KB [row][j] top-1
    __shared__ float s_bm2[RCHUNK * NBLK];                     // 8 KB [row][j] top-2
    __shared__ float s_rs32[RCHUNK * NBLK];                    // 8 KB [row][j] partial rs
    __shared__ __align__(8) unsigned char s_bi[RCHUNK * NBLK]; // 2 KB [row][j]

    const int b    = blockIdx.x >> 6;
    const int c    = blockIdx.x & (NCHUNK - 1);
    const int t    = threadIdx.x;
    const int lane = t & 31;
    const int g    = t >> 3;                 // column-block 0..31 owned by thread
    const int l8   = 4 * (lane & 7);         // base idx of this thread within block

    const float ar  = cr[0];
    const float aq  = cq[0];
    const bool same = (ar == aq);
    const float arl = ar * LOG2E;
    const float aql = aq * LOG2E;

    const float4* p = reinterpret_cast<const float4*>(
        x + ((size_t)b * R + (size_t)c * RCHUNK) * Q) + t;

    float4 acc = make_float4(0.f, 0.f, 0.f, 0.f);

    #pragma unroll 1
    for (int r = 0; r < RCHUNK; r += 8) {
        float4 v[8];
        #pragma unroll
        for (int k = 0; k < 8; ++k)
            v[k] = __ldcg(p + k * (Q / 4));
        p += 8 * (Q / 4);

        #pragma unroll
        for (int k = 0; k < 8; ++k) {
            float4 w = v[k];

            float e0 = ex2f(arl * w.x);
            float e1 = ex2f(arl * w.y);
            float e2 = ex2f(arl * w.z);
            float e3 = ex2f(arl * w.w);
            acc.x += e0; acc.y += e1; acc.z += e2; acc.w += e3;

            float rsl;
            if (same) {
                rsl = (e0 + e1) + (e2 + e3);
            } else {
                rsl = ex2f(aql * w.x) + ex2f(aql * w.y)
                    + ex2f(aql * w.z) + ex2f(aql * w.w);
            }

            // per-thread top-2 of the 4 components
            float hi1 = fmaxf(w.x, w.y), lo1 = fminf(w.x, w.y);
            float hi2 = fmaxf(w.z, w.w), lo2 = fminf(w.z, w.w);
            float m1 = fmaxf(hi1, hi2);
            float m2 = fmaxf(fminf(hi1, hi2), fmaxf(lo1, lo2));

            // shared 3-level butterfly (8 lanes = 32 columns): rs + exact top-2
            #pragma unroll
            for (int o = 4; o > 0; o >>= 1) {
                rsl += __shfl_xor_sync(0xFFFFFFFFu, rsl, o);
                float om1 = __shfl_xor_sync(0xFFFFFFFFu, m1, o);
                float om2 = __shfl_xor_sync(0xFFFFFFFFu, m2, o);
                m2 = fmaxf(fminf(m1, om1), fmaxf(m2, om2));
                m1 = fmaxf(m1, om1);
            }

            // witness index: some lane's component equals m1 exactly
            int idx = -1;
            if (w.x == m1) idx = l8;
            if (w.y == m1) idx = l8 + 1;
            if (w.z == m1) idx = l8 + 2;
            if (w.w == m1) idx = l8 + 3;
            if (idx >= 0) s_bi[(r + k) * NBLK + g] = (unsigned char)idx;

            if ((lane & 7) == 0) {
                s_bm[(r + k) * NBLK + g]   = m1;
                s_bm2[(r + k) * NBLK + g]  = m2;
                s_rs32[(r + k) * NBLK + g] = rsl;
            }
        }
    }
    __syncthreads();

    // column sums -> L2-resident atomic accumulator (64 KB total)
    float* cs = g_colsum + (size_t)b * Q + 4 * t;
    atomicAdd(cs + 0, acc.x);
    atomicAdd(cs + 1, acc.y);
    atomicAdd(cs + 2, acc.z);
    atomicAdd(cs + 3, acc.w);

    // finish row sums: thread t<64 sums 32 partials of row t (rotated)
    if (t < RCHUNK) {
        float s = 0.f;
        #pragma unroll
        for (int i = 0; i < NBLK; ++i)
            s += s_rs32[t * NBLK + ((i + t) & (NBLK - 1))];
        g_rs[b * R + c * RCHUNK + t] = s;
    }

    // headers out: exact m1 (float) + packed (quantized m2 delta, witness)
    const size_t rowbase = (size_t)b * R + (size_t)c * RCHUNK;
    float4* gbm = reinterpret_cast<float4*>(g_bm + rowbase * NBLK);
    const float4* sb = reinterpret_cast<const float4*>(s_bm);
    gbm[t]       = sb[t];
    gbm[t + 256] = sb[t + 256];

    // pack 8 entries per thread: aux = (d << 8) | bi, d = floor((m1-m2)*32) sat
    {
        unsigned int pk[4];
        #pragma unroll
        for (int i = 0; i < 4; ++i) {
            int e0 = 8 * t + 2 * i;
            float d0f = (s_bm[e0] - s_bm2[e0]) * M2SCALE;
            float d1f = (s_bm[e0 + 1] - s_bm2[e0 + 1]) * M2SCALE;
            unsigned int d0 = min(255u, (unsigned int)d0f);   // floor: bound stays valid
            unsigned int d1 = min(255u, (unsigned int)d1f);
            unsigned int a0 = (d0 << 8) | s_bi[e0];
            unsigned int a1 = (d1 << 8) | s_bi[e0 + 1];
            pk[i] = a0 | (a1 << 16);
        }
        reinterpret_cast<uint4*>(g_aux + rowbase * NBLK)[t] =
            make_uint4(pk[0], pk[1], pk[2], pk[3]);
    }
}

// ---------------------------------------------------------------------------
// Kernel 2: Cref = log(colsum); per-32-col Cmin. Re-zeroes g_colsum after
// reading so the next launch (graph replay) starts from zeros again.
// ---------------------------------------------------------------------------
__global__ __launch_bounds__(256) void qatm_cred()
{
    const int b    = blockIdx.x >> 2;
    const int col  = ((blockIdx.x & 3) << 8) + threadIdx.x;
    const int lane = threadIdx.x & 31;

    float s = g_colsum[b * Q + col];
    g_colsum[b * Q + col] = 0.f;          // reset for next launch

    float lg = __logf(s);
    g_creflog[b * Q + col] = lg;

    float mn = lg;
    #pragma unroll
    for (int o = 16; o > 0; o >>= 1)
        mn = fminf(mn, __shfl_xor_sync(0xFFFFFFFFu, mn, o));
    if (lane == 0)
        g_cmin[b * NBLK + (col >> 5)] = mn;
}

// ---------------------------------------------------------------------------
// Pass 2: warp per EIGHT rows; block covers 64 rows of one batch.
// Batch Cref table staged in smem. Witness gather = LDS scatter; survivor
// Cref reads conflict-free LDS. Final per-row butterfly only for rows that
// actually had survivors (others already hold the warp-uniform lb).
//   lb = max_j (cc*bm_j - Cref[witness_j])       (covers all top elements)
//   block j scanned ONLY if cc*(bm_j - d_j/32) - Cmin_j > lb
//   (bm_j - d_j/32 >= true second max >= every non-top element).
// ---------------------------------------------------------------------------
__global__ __launch_bounds__(256) void qatm_p2(
    const float* __restrict__ x,
    const float* __restrict__ cr,
    const float* __restrict__ cq,
    float* __restrict__ out)
{
    __shared__ __align__(16) float s_clog[Q];   // this batch's Cref table

    const int wid  = threadIdx.x >> 5;
    const int lane = threadIdx.x & 31;
    const int row0 = (blockIdx.x * 8 + wid) * P2ROWS;
    const int b    = row0 >> 12;           // all 64 block rows share a batch

    // stage Cref (coalesced): 256 threads x 1 float4
    reinterpret_cast<float4*>(s_clog)[threadIdx.x] =
        reinterpret_cast<const float4*>(g_creflog + (size_t)b * Q)[threadIdx.x];
    __syncthreads();

    const float cc = cr[0] + cq[0];
    const float cmin = __ldg(&g_cmin[b * NBLK + lane]);

    // round 1: all header loads independent
    float bm[P2ROWS];
    unsigned int ax[P2ROWS];
    #pragma unroll
    for (int r = 0; r < P2ROWS; ++r)
        bm[r] = g_bm[(size_t)(row0 + r) * NBLK + lane];
    #pragma unroll
    for (int r = 0; r < P2ROWS; ++r)
        ax[r] = g_aux[(size_t)(row0 + r) * NBLK + lane];
    float rr = (lane < P2ROWS) ? __ldg(&g_rs[row0 + lane]) : 1.f;

    // witness Cref via smem (bank = bi mod 32, mild conflicts)
    float cw[P2ROWS];
    #pragma unroll
    for (int r = 0; r < P2ROWS; ++r)
        cw[r] = s_clog[lane * 32 + (ax[r] & 255u)];

    // exact witness values -> per-row lb; quantized second-max upper bounds
    float m[P2ROWS];
    unsigned k[P2ROWS], had[P2ROWS];
    #pragma unroll
    for (int r = 0; r < P2ROWS; ++r)
        m[r] = fmaf(cc, bm[r], -cw[r]);

    #pragma unroll
    for (int o = 16; o > 0; o >>= 1) {
        #pragma unroll
        for (int r = 0; r < P2ROWS; ++r)
            m[r] = fmaxf(m[r], __shfl_xor_sync(0xFFFFFFFFu, m[r], o));
    }

    #pragma unroll
    for (int r = 0; r < P2ROWS; ++r) {
        float s = bm[r] - (float)(ax[r] >> 8) * M2INV;   // >= true second max
        k[r] = __ballot_sync(0xFFFFFFFFu, fmaf(cc, s, -cmin) > m[r]);
        had[r] = k[r];
    }

    // survivor drain: up to 8 independent x loads per round; Cref from smem
    unsigned any = k[0] | k[1] | k[2] | k[3] | k[4] | k[5] | k[6] | k[7];
    while (any) {
        int j[P2ROWS];
        #pragma unroll
        for (int r = 0; r < P2ROWS; ++r) {
            j[r] = -1;
            if (k[r]) { j[r] = __ffs(k[r]) - 1; k[r] &= k[r] - 1; }
        }
        float a[P2ROWS];
        #pragma unroll
        for (int r = 0; r < P2ROWS; ++r)
            a[r] = (j[r] >= 0) ? __ldcs(x + (size_t)(row0 + r) * Q + j[r] * 32 + lane) : 0.f;
        #pragma unroll
        for (int r = 0; r < P2ROWS; ++r)
            if (j[r] >= 0) {
                float cf = s_clog[j[r] * 32 + lane];   // conflict-free LDS
                m[r] = fmaxf(m[r], fmaf(cc, a[r], -cf));
            }
        any = k[0] | k[1] | k[2] | k[3] | k[4] | k[5] | k[6] | k[7];
    }

    // final reduce only where survivors touched m[r] (else m[r] is uniform lb)
    #pragma unroll
    for (int r = 0; r < P2ROWS; ++r) {
        if (had[r]) {
            #pragma unroll
            for (int o = 16; o > 0; o >>= 1)
                m[r] = fmaxf(m[r], __shfl_xor_sync(0xFFFFFFFFu, m[r], o));
        }
    }

    if (lane < P2ROWS) {
        float mm = m[0];
        #pragma unroll
        for (int r = 1; r < P2ROWS; ++r)
            if (lane == r) mm = m[r];
        out[row0 + lane] = __expf(0.5f * (mm - __logf(rr)));
    }
}

// ---------------------------------------------------------------------------
extern "C" void kernel_launch(void* const* d_in, const int* in_sizes, int n_in,
                              void* d_out, int out_size)
{
    const float* x  = (const float*)d_in[0];
    const float* cr = (const float*)d_in[1];
    const float* cq = (const float*)d_in[2];
    float* out = (float*)d_out;

    const int B = in_sizes[0] / (R * Q);   // 16

    qatm_pass1<<<B * NCHUNK, 256>>>(x, cr, cq);
    qatm_cred<<<B * 4, 256>>>();
    qatm_p2<<<B * R / (8 * P2ROWS), 256>>>(x, cr, cq, out);
}